// round 15
// baseline (speedup 1.0000x reference)
#include <cuda_runtime.h>
#include <cuda_bf16.h>
#include <math.h>
#include <stdint.h>

// ---------------------------------------------------------------------------
// WaveNet inference, flat-time-domain form, bf16-split mma.sync GEMMs.
// R13 structure (direct-LDG mainloop, 128-thr blocks, virtual padding) with
// hi/lo activation planes INTERLEAVED column-wise: one LDG.64 per B fetch.
//
//   buf[(c>>1)*PSTR + 2*t + 0] = bf16 pair (c,c+1) HI
//   buf[(c>>1)*PSTR + 2*t + 1] = bf16 pair (c,c+1) LO      (PSTR = 2*LSTR)
//
// Per layer i (d = 2^(i%10)):
//   p = (-L) mod d   (virtual pad via load masking)
//   gated[t] = tanh(Wf0 x[t] + Wf1 x[t+d]) * sigmoid(Wg0 x[t] + Wg1 x[t+d])
//   skip[-Nout:] += Wskip * gated
//   x_new[t] = Wres * gated[t] + x[t+d]
// End: out = end2 @ relu(end1 @ relu(skip) + b1) + b2, last 4096 cols.
//
// Numerics: v = hi + lo (both bf16); GEMM = Ahi*Bhi + Ahi*Blo + Alo*Bhi with
// fp32 accumulate (~2^-16 relative error). Identical to the 2785us baseline.
// ---------------------------------------------------------------------------

#define LSTR   7168
#define PSTR   (2 * LSTR)
#define ECOL   7168
#define NLAYER 30

// activations: interleaved hi/lo, 128 pair-rows x PSTR u32
__device__ uint32_t g_xA[128 * PSTR];
__device__ uint32_t g_xB[128 * PSTR];
__device__ uint32_t g_g [128 * PSTR];
// fp32 buffers
__device__ float g_sk[512 * LSTR];
__device__ float g_h1[512 * 4096];
// fragment-packed weights (u32 = 2 bf16)
__device__ uint32_t g_wfgHi[NLAYER * 512 * 512 / 2];
__device__ uint32_t g_wfgLo[NLAYER * 512 * 512 / 2];
__device__ uint32_t g_resHi[NLAYER * 256 * 256 / 2];
__device__ uint32_t g_resLo[NLAYER * 256 * 256 / 2];
__device__ uint32_t g_skpHi[NLAYER * 512 * 256 / 2];
__device__ uint32_t g_skpLo[NLAYER * 512 * 256 / 2];

// ---------------------------------------------------------------------------
__device__ __forceinline__ void split2(float v, unsigned short& h, unsigned short& l) {
    __nv_bfloat16 bh = __float2bfloat16(v);
    float rest = v - __bfloat162float(bh);
    __nv_bfloat16 bl = __float2bfloat16(rest);
    h = __bfloat16_as_ushort(bh);
    l = __bfloat16_as_ushort(bl);
}
__device__ __forceinline__ float bf2f(unsigned short u) {
    return __bfloat162float(__ushort_as_bfloat16(u));
}

__device__ __forceinline__ void mma16816(float* c, const uint4& a, uint32_t b0, uint32_t b1) {
    asm volatile(
        "mma.sync.aligned.m16n8k16.row.col.f32.bf16.bf16.f32 "
        "{%0,%1,%2,%3},{%4,%5,%6,%7},{%8,%9},{%0,%1,%2,%3};\n"
        : "+f"(c[0]), "+f"(c[1]), "+f"(c[2]), "+f"(c[3])
        : "r"(a.x), "r"(a.y), "r"(a.z), "r"(a.w), "r"(b0), "r"(b1));
}

// ---------------------------------------------------------------------------
// Fragment packing (u32 index = ((kt*Mt + mt)*32 + lane)*4 + r).
// ---------------------------------------------------------------------------
__global__ void fragpack_gate(const float* __restrict__ fw, const float* __restrict__ gw,
                              uint32_t* __restrict__ Phi, uint32_t* __restrict__ Plo) {
    const int PER = 512 * 512 / 2;
    int idx = blockIdx.x * blockDim.x + threadIdx.x;
    if (idx >= NLAYER * PER) return;
    int i = idx / PER, rem = idx % PER;
    int r = rem & 3, lane = (rem >> 2) & 31, tile = rem >> 7;
    int mt = tile & 31, kt = tile >> 5;           // Mt = 32
    int g = lane >> 2, tg = lane & 3;
    int row = mt * 16 + g + ((r & 1) ? 8 : 0);    // 0..511 : F rows then G rows
    int k2  = kt * 16 + tg * 2 + ((r & 2) ? 8 : 0); // 0..511 : tap0 then tap1
    int tap = k2 >> 8, k = k2 & 255;
    float v0, v1;
    if (row < 256) {
        v0 = fw[(((size_t)i * 256 + row) * 256 + k) * 2 + tap];
        v1 = fw[(((size_t)i * 256 + row) * 256 + k + 1) * 2 + tap];
    } else {
        v0 = gw[(((size_t)i * 256 + row - 256) * 256 + k) * 2 + tap];
        v1 = gw[(((size_t)i * 256 + row - 256) * 256 + k + 1) * 2 + tap];
    }
    unsigned short h0, l0, h1, l1;
    split2(v0, h0, l0); split2(v1, h1, l1);
    Phi[idx] = (uint32_t)h0 | ((uint32_t)h1 << 16);
    Plo[idx] = (uint32_t)l0 | ((uint32_t)l1 << 16);
}

__global__ void fragpack_std(const float* __restrict__ W, int M, int K,
                             uint32_t* __restrict__ Phi, uint32_t* __restrict__ Plo) {
    int per = M * K / 2;
    int idx = blockIdx.x * blockDim.x + threadIdx.x;
    if (idx >= NLAYER * per) return;
    int i = idx / per, rem = idx % per;
    int Mt = M / 16;
    int r = rem & 3, lane = (rem >> 2) & 31, tile = rem >> 7;
    int mt = tile % Mt, kt = tile / Mt;
    int g = lane >> 2, tg = lane & 3;
    int row = mt * 16 + g + ((r & 1) ? 8 : 0);
    int k   = kt * 16 + tg * 2 + ((r & 2) ? 8 : 0);
    const float* Wl = W + (size_t)i * M * K;
    float v0 = Wl[(size_t)row * K + k];
    float v1 = Wl[(size_t)row * K + k + 1];
    unsigned short h0, l0, h1, l1;
    split2(v0, h0, l0); split2(v1, h1, l1);
    Phi[idx] = (uint32_t)h0 | ((uint32_t)h1 << 16);
    Plo[idx] = (uint32_t)l0 | ((uint32_t)l1 << 16);
}

// ---------------------------------------------------------------------------
// Start conv: fp32 SIMT GEMM, writes interleaved hi/lo planes (uint2 stores).
// ---------------------------------------------------------------------------
__global__ void lin_start(const float* __restrict__ W, const float* __restrict__ X,
                          uint32_t* __restrict__ Xp, int N, int col0) {
    const int t0 = blockIdx.x * 64;
    const int m0 = blockIdx.y * 64;
    const int tid = threadIdx.x;
    const int tx = tid & 15, ty = tid >> 4;

    __shared__ float Xs[16][64];
    __shared__ float Ws[64][16];

    float acc[4][4] = {};

    for (int kc = 0; kc < 256; kc += 16) {
#pragma unroll
        for (int j = 0; j < 4; j++) {
            int e = tid + 256 * j;
            int r = e >> 6, c = e & 63;
            int t = t0 + c;
            Xs[r][c] = (t < N) ? X[(size_t)(kc + r) * N + t] : 0.f;
            int mm = e >> 4, rr = e & 15;
            Ws[mm][rr] = W[(size_t)(m0 + mm) * 256 + kc + rr];
        }
        __syncthreads();
#pragma unroll
        for (int r = 0; r < 16; r++) {
            float b[4];
#pragma unroll
            for (int j = 0; j < 4; j++) b[j] = Xs[r][tx * 4 + j];
#pragma unroll
            for (int i = 0; i < 4; i++) {
                float a = Ws[ty * 4 + i][r];
#pragma unroll
                for (int j = 0; j < 4; j++) acc[i][j] += a * b[j];
            }
        }
        __syncthreads();
    }

#pragma unroll
    for (int j = 0; j < 4; j++) {
        int t = t0 + tx * 4 + j;
        if (t >= N) continue;
#pragma unroll
        for (int pi = 0; pi < 2; pi++) {
            int m = m0 + ty * 4 + 2 * pi;     // even channel of the pair
            unsigned short h0, l0, h1, l1;
            split2(acc[2 * pi][j], h0, l0);
            split2(acc[2 * pi + 1][j], h1, l1);
            uint2 w;
            w.x = (uint32_t)h0 | ((uint32_t)h1 << 16);
            w.y = (uint32_t)l0 | ((uint32_t)l1 << 16);
            *(uint2*)(Xp + (size_t)(m >> 1) * PSTR + 2 * (col0 + t)) = w;
        }
    }
}

// ---------------------------------------------------------------------------
// Gate kernel: F,G = W[512x512] @ Xcat, epilogue tanh*sigmoid, split-store.
// Block 128 thr (4 warps, 1Mx4N). Block tile M=32(F)+32(G), N=128.
// B fetches are LDG.64 ({hi,lo} together). Virtual padding via mask.
// grid (ceil(Nout/128), 8).
// ---------------------------------------------------------------------------
__global__ __launch_bounds__(128) void gate_mma(
    const uint32_t* __restrict__ Whi, const uint32_t* __restrict__ Wlo,
    const uint32_t* __restrict__ X,
    uint32_t* __restrict__ G,
    int L, int d, int p)
{
    const int Nout = L - d;
    const int xbase = ECOL - L;
    const int obase = ECOL - Nout;
    const int tid = threadIdx.x;
    const int lane = tid & 31, wn = tid >> 5;        // 4 warps
    const int g = lane >> 2, tg = lane & 3;
    const int mF = blockIdx.y * 32;                  // 0..224 (F rows)
    const int n_warp = blockIdx.x * 128 + wn * 32;

    const uint4* Whi4 = (const uint4*)Whi;
    const uint4* Wlo4 = (const uint4*)Wlo;

    float CF[2][4][4] = {};
    float CG[2][4][4] = {};

    for (int kt = 0; kt < 32; ++kt) {
        const bool tap1 = (kt >= 16);
        const int shift = tap1 ? d : 0;
        const int krow = (kt & 15) * 8 + tg;
        uint32_t bh0[4], bh1[4], bl0[4], bl1[4];
#pragma unroll
        for (int nt = 0; nt < 4; ++nt) {
            int n = n_warp + nt * 8 + g;
            bool ok = (n < Nout) && (tap1 || n >= p);
            int col = xbase + n + shift;
            uint2 v0 = make_uint2(0u, 0u), v1 = make_uint2(0u, 0u);
            if (ok) {
                v0 = *(const uint2*)(X + (size_t)krow * PSTR + 2 * col);
                v1 = *(const uint2*)(X + (size_t)(krow + 4) * PSTR + 2 * col);
            }
            bh0[nt] = v0.x; bl0[nt] = v0.y;
            bh1[nt] = v1.x; bl1[nt] = v1.y;
        }
#pragma unroll
        for (int mt = 0; mt < 2; ++mt) {
            int mtF = (mF >> 4) + mt;
            uint4 aFh = Whi4[(kt * 32 + mtF) * 32 + lane];
            uint4 aFl = Wlo4[(kt * 32 + mtF) * 32 + lane];
            uint4 aGh = Whi4[(kt * 32 + mtF + 16) * 32 + lane];
            uint4 aGl = Wlo4[(kt * 32 + mtF + 16) * 32 + lane];
#pragma unroll
            for (int nt = 0; nt < 4; ++nt) {
                mma16816(CF[mt][nt], aFh, bh0[nt], bh1[nt]);
                mma16816(CF[mt][nt], aFh, bl0[nt], bl1[nt]);
                mma16816(CF[mt][nt], aFl, bh0[nt], bh1[nt]);
                mma16816(CG[mt][nt], aGh, bh0[nt], bh1[nt]);
                mma16816(CG[mt][nt], aGh, bl0[nt], bl1[nt]);
                mma16816(CG[mt][nt], aGl, bh0[nt], bh1[nt]);
            }
        }
    }

    unsigned short* GS = (unsigned short*)G;
#pragma unroll
    for (int mt = 0; mt < 2; ++mt)
#pragma unroll
        for (int nt = 0; nt < 4; ++nt)
#pragma unroll
            for (int r = 0; r < 4; ++r) {
                int n = n_warp + nt * 8 + 2 * tg + (r & 1);
                if (n >= Nout) continue;
                int m = mF + mt * 16 + g + ((r >= 2) ? 8 : 0);
                float f = CF[mt][nt][r];
                float q = CG[mt][nt][r];
                float fv = 2.f / (1.f + __expf(-2.f * f)) - 1.f;
                float sv = 1.f / (1.f + __expf(-q));
                float val = fv * sv;
                unsigned short h, l;
                split2(val, h, l);
                size_t base = ((size_t)(m >> 1) * PSTR + 2 * (obase + n)) * 2;
                GS[base + (m & 1)]     = h;
                GS[base + 2 + (m & 1)] = l;
            }
}

// ---------------------------------------------------------------------------
// Res+Skip kernel: M=768 (res 0..255, skip 256..767), K=256 over gated.
// Block 128 thr (4 warps, 1Mx4N). Block tile M=64, N=128. LDG.64 B fetches.
// grid (ceil(Nout/128), 12).
// ---------------------------------------------------------------------------
__global__ __launch_bounds__(128) void resskip_mma(
    const uint32_t* __restrict__ RHi, const uint32_t* __restrict__ RLo,
    const uint32_t* __restrict__ SHi, const uint32_t* __restrict__ SLo,
    const uint32_t* __restrict__ G,
    const uint32_t* __restrict__ Xold,
    uint32_t* __restrict__ Xnew,
    float* __restrict__ skip, int Nout, int first)
{
    const int gbase = ECOL - Nout;
    const int tid = threadIdx.x;
    const int lane = tid & 31, wn = tid >> 5;
    const int g = lane >> 2, tg = lane & 3;
    const int m_warp = blockIdx.y * 64;              // 0..704
    const int n_warp = blockIdx.x * 128 + wn * 32;
    const bool isres = m_warp < 256;

    const uint4* Ah4;
    const uint4* Al4;
    int mtBase, Mt;
    if (isres) { Ah4 = (const uint4*)RHi; Al4 = (const uint4*)RLo; mtBase = m_warp >> 4;         Mt = 16; }
    else       { Ah4 = (const uint4*)SHi; Al4 = (const uint4*)SLo; mtBase = (m_warp - 256) >> 4; Mt = 32; }

    float C[4][4][4] = {};

    for (int kt = 0; kt < 16; ++kt) {
        const int krow = kt * 8 + tg;
        uint32_t bh0[4], bh1[4], bl0[4], bl1[4];
#pragma unroll
        for (int nt = 0; nt < 4; ++nt) {
            int n = n_warp + nt * 8 + g;
            bool ok = n < Nout;
            int col = gbase + n;
            uint2 v0 = make_uint2(0u, 0u), v1 = make_uint2(0u, 0u);
            if (ok) {
                v0 = *(const uint2*)(G + (size_t)krow * PSTR + 2 * col);
                v1 = *(const uint2*)(G + (size_t)(krow + 4) * PSTR + 2 * col);
            }
            bh0[nt] = v0.x; bl0[nt] = v0.y;
            bh1[nt] = v1.x; bl1[nt] = v1.y;
        }
#pragma unroll
        for (int mt = 0; mt < 4; ++mt) {
            uint4 ah = Ah4[(kt * Mt + mtBase + mt) * 32 + lane];
            uint4 al = Al4[(kt * Mt + mtBase + mt) * 32 + lane];
#pragma unroll
            for (int nt = 0; nt < 4; ++nt) {
                mma16816(C[mt][nt], ah, bh0[nt], bh1[nt]);
                mma16816(C[mt][nt], ah, bl0[nt], bl1[nt]);
                mma16816(C[mt][nt], al, bh0[nt], bh1[nt]);
            }
        }
    }

    const unsigned short* XoS = (const unsigned short*)Xold;
    unsigned short* XnS = (unsigned short*)Xnew;
#pragma unroll
    for (int mt = 0; mt < 4; ++mt)
#pragma unroll
        for (int nt = 0; nt < 4; ++nt)
#pragma unroll
            for (int r = 0; r < 4; ++r) {
                int n = n_warp + nt * 8 + 2 * tg + (r & 1);
                if (n >= Nout) continue;
                int m = m_warp + mt * 16 + g + ((r >= 2) ? 8 : 0);
                int col = gbase + n;
                float v = C[mt][nt][r];
                if (isres) {
                    size_t base = ((size_t)(m >> 1) * PSTR + 2 * col) * 2;
                    v += bf2f(XoS[base + (m & 1)]) + bf2f(XoS[base + 2 + (m & 1)]);
                    unsigned short h, l;
                    split2(v, h, l);
                    XnS[base + (m & 1)]     = h;
                    XnS[base + 2 + (m & 1)] = l;
                } else {
                    int ms = m - 256;
                    if (!first) v += skip[ms * LSTR + col];
                    skip[ms * LSTR + col] = v;
                }
            }
}

// ---------------------------------------------------------------------------
// SIMT fp32 GEMM for end convs: Y = W[MxK] @ X[KxN] (+bias/relu).
// ---------------------------------------------------------------------------
__global__ void lin_kernel(const float* __restrict__ W,
                           const float* __restrict__ X, int ldx,
                           const float* __restrict__ bias,
                           float* __restrict__ Y, int ldy,
                           int M, int K, int N, int relu_in, int relu_out) {
    const int t0 = blockIdx.x * 64;
    const int m0 = blockIdx.y * 64;
    const int tid = threadIdx.x;
    const int tx = tid & 15, ty = tid >> 4;

    __shared__ float Xs[16][64];
    __shared__ float Ws[64][16];

    float acc[4][4] = {};

    for (int kc = 0; kc < K; kc += 16) {
#pragma unroll
        for (int j = 0; j < 4; j++) {
            int e = tid + 256 * j;
            int r = e >> 6, c = e & 63;
            int t = t0 + c;
            float v = (t < N) ? X[(size_t)(kc + r) * ldx + t] : 0.f;
            if (relu_in) v = fmaxf(v, 0.f);
            Xs[r][c] = v;
            int mm = e >> 4, rr = e & 15;
            Ws[mm][rr] = W[(size_t)(m0 + mm) * K + kc + rr];
        }
        __syncthreads();
#pragma unroll
        for (int r = 0; r < 16; r++) {
            float b[4];
#pragma unroll
            for (int j = 0; j < 4; j++) b[j] = Xs[r][tx * 4 + j];
#pragma unroll
            for (int i = 0; i < 4; i++) {
                float a = Ws[ty * 4 + i][r];
#pragma unroll
                for (int j = 0; j < 4; j++) acc[i][j] += a * b[j];
            }
        }
        __syncthreads();
    }

#pragma unroll
    for (int i = 0; i < 4; i++) {
        int m = m0 + ty * 4 + i;
#pragma unroll
        for (int j = 0; j < 4; j++) {
            int t = t0 + tx * 4 + j;
            if (t >= N) continue;
            float v = acc[i][j];
            if (bias) v += bias[m];
            if (relu_out) v = fmaxf(v, 0.f);
            Y[(size_t)m * ldy + t] = v;
        }
    }
}

// ---------------------------------------------------------------------------
// Host orchestration (graph-capturable: kernel launches only).
// ---------------------------------------------------------------------------
extern "C" void kernel_launch(void* const* d_in, const int* in_sizes, int n_in,
                              void* d_out, int out_size) {
    (void)in_sizes; (void)n_in; (void)out_size;
    const float* input    = (const float*)d_in[0];
    const float* start_w  = (const float*)d_in[1];
    const float* filter_w = (const float*)d_in[2];
    const float* gate_w   = (const float*)d_in[3];
    const float* res_w    = (const float*)d_in[4];
    const float* skip_w   = (const float*)d_in[5];
    const float* end1_w   = (const float*)d_in[6];
    const float* end1_b   = (const float*)d_in[7];
    const float* end2_w   = (const float*)d_in[8];
    const float* end2_b   = (const float*)d_in[9];

    uint32_t *xA, *xB, *gb;
    uint32_t *wfgHi, *wfgLo, *resHi, *resLo, *skpHi, *skpLo;
    float *sk, *h1;
    cudaGetSymbolAddress((void**)&xA, g_xA);
    cudaGetSymbolAddress((void**)&xB, g_xB);
    cudaGetSymbolAddress((void**)&gb, g_g);
    cudaGetSymbolAddress((void**)&wfgHi, g_wfgHi);
    cudaGetSymbolAddress((void**)&wfgLo, g_wfgLo);
    cudaGetSymbolAddress((void**)&resHi, g_resHi);
    cudaGetSymbolAddress((void**)&resLo, g_resLo);
    cudaGetSymbolAddress((void**)&skpHi, g_skpHi);
    cudaGetSymbolAddress((void**)&skpLo, g_skpLo);
    cudaGetSymbolAddress((void**)&sk, g_sk);
    cudaGetSymbolAddress((void**)&h1, g_h1);

    // Weight fragment packing (every call; deterministic).
    {
        int n = NLAYER * 512 * 512 / 2;
        fragpack_gate<<<(n + 255) / 256, 256>>>(filter_w, gate_w, wfgHi, wfgLo);
        n = NLAYER * 256 * 256 / 2;
        fragpack_std<<<(n + 255) / 256, 256>>>(res_w, 256, 256, resHi, resLo);
        n = NLAYER * 512 * 256 / 2;
        fragpack_std<<<(n + 255) / 256, 256>>>(skip_w, 512, 256, skpHi, skpLo);
    }

    // Start conv: fp32 SIMT GEMM writing interleaved split planes.
    lin_start<<<dim3((7165 + 63) / 64, 4), 256>>>(
        start_w, input, xA, 7165, ECOL - 7165);

    int L = 7165;
    uint32_t *xc = xA, *xn = xB;

    for (int i = 0; i < NLAYER; i++) {
        int d = 1 << (i % 10);
        int p = (d - (L % d)) % d;
        L += p;                     // virtual pad (masked in gate loads)
        int Nout = L - d;

        dim3 gg((Nout + 127) / 128, 8);
        gate_mma<<<gg, 128>>>(wfgHi + (size_t)i * 131072, wfgLo + (size_t)i * 131072,
                              xc, gb, L, d, p);

        dim3 gr((Nout + 127) / 128, 12);
        resskip_mma<<<gr, 128>>>(resHi + (size_t)i * 32768, resLo + (size_t)i * 32768,
                                 skpHi + (size_t)i * 65536, skpLo + (size_t)i * 65536,
                                 gb, xc, xn, sk, Nout, i == 0 ? 1 : 0);
        uint32_t* t = xc; xc = xn; xn = t;
        L = Nout;
    }

    // End head on last 4096 columns (fp32 SIMT).
    lin_kernel<<<dim3(64, 8), 256>>>(
        end1_w, sk + (ECOL - 4096), LSTR, end1_b, h1, 4096,
        512, 512, 4096, 1, 1);
    lin_kernel<<<dim3(64, 4), 256>>>(
        end2_w, h1, 4096, end2_b, (float*)d_out, 4096,
        256, 512, 4096, 0, 0);
}